// round 1
// baseline (speedup 1.0000x reference)
#include <cuda_runtime.h>
#include <cuda_bf16.h>
#include <cstdint>

// FlaxHouseholderRoPE: B=2, S=4096, H=32, D=128, R=2, fp32.
// Inputs (metadata order): q (B,S,H,D) f32, k (B,S,H,D) f32, pos (S) f32,
//                          reflectors (H,R,D) f32.
// Output: concat(q_out, k_out), each (B,S,H,D) f32.
//
// One warp per (tensor, b, s, h) vector: lane l owns float4 = elements [4l, 4l+4).
// Two sequential Householder reflections with warp-shfl reduction of (dot, |v|^2),
// then interleaved-pair RoPE computed in-register.

#define BB 2
#define SS 4096
#define HH 32
#define DD 128
#define NVEC (BB * SS * HH)   // 262144 vectors per tensor

__global__ __launch_bounds__(256)
void hh_rope_kernel(const float* __restrict__ q,
                    const float* __restrict__ k,
                    const float* __restrict__ pos,
                    const float* __restrict__ refl,
                    float* __restrict__ out) {
    const int gwarp = (blockIdx.x * blockDim.x + threadIdx.x) >> 5;  // 0 .. 2*NVEC-1
    const int lane  = threadIdx.x & 31;
    if (gwarp >= 2 * NVEC) return;

    const int is_k  = (gwarp >= NVEC);
    const int idx   = is_k ? (gwarp - NVEC) : gwarp;     // (b*S + s)*H + h
    const float* __restrict__ src = is_k ? k : q;

    const int h = idx & (HH - 1);          // H = 32
    const int s = (idx >> 5) & (SS - 1);   // S = 4096

    // ---- load 4 consecutive floats per lane (coalesced 128B per warp) ----
    const float4* src4 = reinterpret_cast<const float4*>(src) + (size_t)idx * (DD / 4);
    float4 x = src4[lane];

    // ---- two sequential Householder reflections ----
    #pragma unroll
    for (int r = 0; r < 2; ++r) {
        const float4 v = reinterpret_cast<const float4*>(refl)[(h * 2 + r) * (DD / 4) + lane];
        float dot = x.x * v.x + x.y * v.y + x.z * v.z + x.w * v.w;
        float sq  = v.x * v.x + v.y * v.y + v.z * v.z + v.w * v.w;
        #pragma unroll
        for (int o = 16; o; o >>= 1) {
            dot += __shfl_xor_sync(0xffffffffu, dot, o);
            sq  += __shfl_xor_sync(0xffffffffu, sq,  o);
        }
        const float coef = 2.0f * dot / (sq + 1e-6f);
        x.x -= coef * v.x;  x.y -= coef * v.y;
        x.z -= coef * v.z;  x.w -= coef * v.w;
    }

    // ---- RoPE (interleaved pairs) ----
    // pair indices for this lane's float4: i0 = 2*lane, i1 = 2*lane + 1
    // inv_freq(i) = 10000^(-2i/128) = exp2(-(2i/128) * log2(10000))
    const float p = pos[s];
    const float LOG2_BASE = 13.287712379549449f;  // log2(10000)
    const int   i0 = lane * 2;
    const float f0 = exp2f(-(float)(2 * i0)     * (1.0f / 128.0f) * LOG2_BASE);
    const float f1 = exp2f(-(float)(2 * i0 + 2) * (1.0f / 128.0f) * LOG2_BASE);

    float s0, c0, s1, c1;
    sincosf(p * f0, &s0, &c0);
    sincosf(p * f1, &s1, &c1);

    float4 o;
    o.x = x.x * c0 - x.y * s0;
    o.y = x.x * s0 + x.y * c0;
    o.z = x.z * c1 - x.w * s1;
    o.w = x.z * s1 + x.w * c1;

    // out layout: [q_out | k_out] contiguous -> global vector id == gwarp
    float4* dst = reinterpret_cast<float4*>(out) + (size_t)gwarp * (DD / 4);
    dst[lane] = o;
}

extern "C" void kernel_launch(void* const* d_in, const int* in_sizes, int n_in,
                              void* d_out, int out_size) {
    const float* q    = (const float*)d_in[0];
    const float* k    = (const float*)d_in[1];
    const float* pos  = (const float*)d_in[2];
    const float* refl = (const float*)d_in[3];
    float* out = (float*)d_out;

    const int total_warps = 2 * NVEC;            // 524288
    const int threads = 256;                     // 8 warps per block
    const int blocks  = (total_warps * 32) / threads;  // 65536
    hh_rope_kernel<<<blocks, threads>>>(q, k, pos, refl, out);
}

// round 2
// speedup vs baseline: 1.4330x; 1.4330x over previous
#include <cuda_runtime.h>
#include <cuda_bf16.h>
#include <cstdint>

// FlaxHouseholderRoPE: B=2, S=4096, H=32, D=128, R=2, fp32.
// Inputs: q (B,S,H,D), k (B,S,H,D), pos (S), reflectors (H,R,D)  [all f32]
// Output: concat(q_out, k_out).
//
// Prologue kernel:
//   - tab4[s][j] = (cos(a_{2j}), sin(a_{2j}), cos(a_{2j+1}), sin(a_{2j+1})),
//     a_i = pos[s] * base^(-2i/128).  2 MB, L2-resident.
//   - wrefl[h][r][:] = 2*v/(|v|^2+eps).  32 KB, L1-resident.
// Main kernel: one warp per (b,s,h); processes q AND k. Householder via
// dot-only butterfly (w precomputed), RoPE via table. No MUFU in hot loop.

#define BB 2
#define SS 4096
#define HH 32
#define DD 128
#define NVEC (BB * SS * HH)        // 262144 vector-pairs
#define TAB_BLOCKS 512             // 512*256 threads = 131072 = 4096*32 float4s

__device__ float4 g_tab[SS * 32];      // (cos,sin,cos,sin) per (s, lane)
__device__ float4 g_wrefl[HH * 2 * 32];

__global__ __launch_bounds__(256)
void prologue_kernel(const float* __restrict__ pos,
                     const float* __restrict__ refl) {
    if (blockIdx.x < TAB_BLOCKS) {
        // ---- cos/sin table ----
        const int j = blockIdx.x * 256 + threadIdx.x;   // 0 .. 131071
        const int s = j >> 5;
        const int t = j & 31;                            // lane-slot: pairs 2t, 2t+1
        const float p = pos[s];
        const float LOG2_BASE = 13.287712379549449f;     // log2(10000)
        const float f0 = exp2f(-(float)(4 * t)     * (1.0f / 128.0f) * LOG2_BASE);
        const float f1 = exp2f(-(float)(4 * t + 2) * (1.0f / 128.0f) * LOG2_BASE);
        float s0, c0, s1, c1;
        sincosf(p * f0, &s0, &c0);
        sincosf(p * f1, &s1, &c1);
        g_tab[j] = make_float4(c0, s0, c1, s1);
    } else {
        // ---- scaled reflectors: w = 2*v / (|v|^2 + eps) ----
        const int wb   = blockIdx.x - TAB_BLOCKS;
        const int warp = wb * 8 + ((int)threadIdx.x >> 5);   // 0 .. 63 rows (H*R)
        const int lane = threadIdx.x & 31;
        if (warp < HH * 2) {
            const float4 v = reinterpret_cast<const float4*>(refl)[warp * 32 + lane];
            float sq = v.x * v.x + v.y * v.y + v.z * v.z + v.w * v.w;
            #pragma unroll
            for (int o = 16; o; o >>= 1) sq += __shfl_xor_sync(0xffffffffu, sq, o);
            const float sc = 2.0f / (sq + 1e-6f);
            g_wrefl[warp * 32 + lane] = make_float4(v.x * sc, v.y * sc, v.z * sc, v.w * sc);
        }
    }
}

__global__ __launch_bounds__(256)
void hh_rope_kernel(const float* __restrict__ q,
                    const float* __restrict__ k,
                    const float* __restrict__ refl,
                    float* __restrict__ out) {
    const int idx  = (blockIdx.x * blockDim.x + threadIdx.x) >> 5;  // (b*S+s)*H + h
    const int lane = threadIdx.x & 31;

    const int h = idx & (HH - 1);
    const int s = (idx >> 5) & (SS - 1);

    // ---- streamed loads (coalesced LDG.128) ----
    float4 xq = reinterpret_cast<const float4*>(q)[(size_t)idx * 32 + lane];
    float4 xk = reinterpret_cast<const float4*>(k)[(size_t)idx * 32 + lane];

    // ---- two Householder reflections on both tensors ----
    #pragma unroll
    for (int r = 0; r < 2; ++r) {
        const int row = (h * 2 + r) * 32 + lane;
        const float4 v = reinterpret_cast<const float4*>(refl)[row];  // L1 hit
        const float4 w = g_wrefl[row];                                 // L1 hit
        float dq = xq.x * v.x + xq.y * v.y + xq.z * v.z + xq.w * v.w;
        float dk = xk.x * v.x + xk.y * v.y + xk.z * v.z + xk.w * v.w;
        #pragma unroll
        for (int o = 16; o; o >>= 1) {
            dq += __shfl_xor_sync(0xffffffffu, dq, o);
            dk += __shfl_xor_sync(0xffffffffu, dk, o);
        }
        xq.x -= dq * w.x;  xq.y -= dq * w.y;  xq.z -= dq * w.z;  xq.w -= dq * w.w;
        xk.x -= dk * w.x;  xk.y -= dk * w.y;  xk.z -= dk * w.z;  xk.w -= dk * w.w;
    }

    // ---- RoPE via table (L1 broadcast across the block's 8 warps) ----
    const float4 cs = g_tab[s * 32 + lane];   // (c0, s0, c1, s1)

    float4 oq, ok;
    oq.x = xq.x * cs.x - xq.y * cs.y;
    oq.y = xq.x * cs.y + xq.y * cs.x;
    oq.z = xq.z * cs.z - xq.w * cs.w;
    oq.w = xq.z * cs.w + xq.w * cs.z;
    ok.x = xk.x * cs.x - xk.y * cs.y;
    ok.y = xk.x * cs.y + xk.y * cs.x;
    ok.z = xk.z * cs.z - xk.w * cs.w;
    ok.w = xk.z * cs.w + xk.w * cs.z;

    float4* out4 = reinterpret_cast<float4*>(out);
    out4[(size_t)idx * 32 + lane]                       = oq;   // q half
    out4[((size_t)NVEC + idx) * 32 + lane]              = ok;   // k half
}

extern "C" void kernel_launch(void* const* d_in, const int* in_sizes, int n_in,
                              void* d_out, int out_size) {
    const float* q    = (const float*)d_in[0];
    const float* k    = (const float*)d_in[1];
    const float* pos  = (const float*)d_in[2];
    const float* refl = (const float*)d_in[3];
    float* out = (float*)d_out;

    // prologue: 512 blocks for table + 8 blocks for scaled reflectors
    prologue_kernel<<<TAB_BLOCKS + 8, 256>>>(pos, refl);

    // main: one warp per (b,s,h) pair -> 262144 warps, 8 warps/block
    hh_rope_kernel<<<NVEC / 8, 256>>>(q, k, refl, out);
}